// round 2
// baseline (speedup 1.0000x reference)
#include <cuda_runtime.h>
#include <math.h>

#define B 4
#define C 256
#define H 128
#define W 128
#define S (H*W)          // 16384
#define NSCALE 4
#define DKC 64           // channels per scale

// ---------------- static scratch (no allocations allowed) ----------------
__device__ float g_q[B*C*S];         // 64MB
__device__ float g_k[B*C*S];
__device__ float g_v[B*C*S];
__device__ float g_att[B*C*S];
__device__ float g_qt[B*1048576];    // 16MB (token layout, reused per scale)
__device__ float g_kt[B*1048576];
__device__ float g_vt[B*1048576];
__device__ float g_ot[B*1048576];
__device__ float g_sc[(long)B*4096*4096];  // 256MB score scratch (max = scale 0)
__device__ float g_mean[C];
__device__ float g_var[C];

// ---------------- generic tiled GEMM ----------------
// C[bz][m][n] = alpha * sum_k A[m][k] * B(k,n)  (+ bias[m])
// A row-major [M,K]. BT=false: B row-major [K,N]. BT=true: B row-major [N,K].
template<bool BT>
__global__ __launch_bounds__(256)
void gemm_kernel(const float* __restrict__ A, long sA,
                 const float* __restrict__ Bm, long sB,
                 float* __restrict__ Cm, long sC,
                 const float* __restrict__ bias,
                 int M, int N, int K, float alpha)
{
    const int bz = blockIdx.z;
    A  += bz * sA;
    Bm += bz * sB;
    Cm += bz * sC;
    const int m0 = blockIdx.y * 64;
    const int n0 = blockIdx.x * 64;

    __shared__ float As[16][68];
    __shared__ float Bs[16][68];

    const int tid = threadIdx.x;
    const int tx = tid & 15, ty = tid >> 4;

    float acc[4][4] = {};

    for (int k0 = 0; k0 < K; k0 += 16) {
        {   // A tile: 64(m) x 16(k), transpose into As[k][m]
            int m  = tid >> 2;
            int k4 = (tid & 3) * 4;
            float4 a = *(const float4*)(A + (long)(m0 + m) * K + (k0 + k4));
            As[k4 + 0][m] = a.x; As[k4 + 1][m] = a.y;
            As[k4 + 2][m] = a.z; As[k4 + 3][m] = a.w;
        }
        if (BT) {   // B tile from [N,K]: 64(n) x 16(k) -> Bs[k][n]
            int n  = tid >> 2;
            int k4 = (tid & 3) * 4;
            float4 v = *(const float4*)(Bm + (long)(n0 + n) * K + (k0 + k4));
            Bs[k4 + 0][n] = v.x; Bs[k4 + 1][n] = v.y;
            Bs[k4 + 2][n] = v.z; Bs[k4 + 3][n] = v.w;
        } else {    // B tile from [K,N]: 16(k) x 64(n) -> Bs[k][n]
            int k  = tid >> 4;
            int n4 = (tid & 15) * 4;
            *(float4*)&Bs[k][n4] = *(const float4*)(Bm + (long)(k0 + k) * N + (n0 + n4));
        }
        __syncthreads();

        #pragma unroll
        for (int kk = 0; kk < 16; kk++) {
            float a[4], bv[4];
            *(float4*)a  = *(const float4*)&As[kk][ty * 4];
            *(float4*)bv = *(const float4*)&Bs[kk][tx * 4];
            #pragma unroll
            for (int i = 0; i < 4; i++)
                #pragma unroll
                for (int j = 0; j < 4; j++)
                    acc[i][j] = fmaf(a[i], bv[j], acc[i][j]);
        }
        __syncthreads();
    }

    #pragma unroll
    for (int i = 0; i < 4; i++) {
        int m = m0 + ty * 4 + i;
        float bb = bias ? bias[m] : 0.0f;
        float4 o;
        o.x = acc[i][0] * alpha + bb;
        o.y = acc[i][1] * alpha + bb;
        o.z = acc[i][2] * alpha + bb;
        o.w = acc[i][3] * alpha + bb;
        *(float4*)(Cm + (long)m * N + n0 + tx * 4) = o;
    }
}

// ---------------- token gather / scatter ----------------
// q[b, base_c+dc, oh*p+ph, ow*p+pw] -> qt[b][n][d], n=oh*outw+ow, d=dc*p*p+ph*p+pw
__global__ void gather_qkv(const float* __restrict__ q, const float* __restrict__ k,
                           const float* __restrict__ v,
                           float* __restrict__ qt, float* __restrict__ kt,
                           float* __restrict__ vt,
                           int base_c, int p, int outw, int Ni, int Di)
{
    long idx = (long)blockIdx.x * blockDim.x + threadIdx.x;  // B*Ni*Di = 4194304
    int d = (int)(idx % Di);
    long t = idx / Di;
    int n = (int)(t % Ni);
    int b = (int)(t / Ni);
    int pp = p * p;
    int dc = d / pp;
    int r  = d % pp;
    int ph = r / p, pw = r % p;
    int oh = n / outw, ow = n % outw;
    int y = oh * p + ph, x = ow * p + pw;
    long src = ((long)(b * C + base_c + dc)) * S + (long)y * W + x;
    qt[idx] = q[src];
    kt[idx] = k[src];
    vt[idx] = v[src];
}

__global__ void scatter_out(const float* __restrict__ ot, float* __restrict__ att,
                            int base_c, int p, int outw, int Ni, int Di)
{
    long idx = (long)blockIdx.x * blockDim.x + threadIdx.x;
    int d = (int)(idx % Di);
    long t = idx / Di;
    int n = (int)(t % Ni);
    int b = (int)(t / Ni);
    int pp = p * p;
    int dc = d / pp;
    int r  = d % pp;
    int ph = r / p, pw = r % p;
    int oh = n / outw, ow = n % outw;
    int y = oh * p + ph, x = ow * p + pw;
    long dst = ((long)(b * C + base_c + dc)) * S + (long)y * W + x;
    att[dst] = ot[idx];
}

// ---------------- row softmax ----------------
__global__ void softmax_kernel(float* __restrict__ Smat, int N)
{
    float* r = Smat + (long)blockIdx.x * N;
    __shared__ float red[256];
    int tid = threadIdx.x;

    float m = -1e30f;
    for (int i = tid; i < N; i += 256) m = fmaxf(m, r[i]);
    red[tid] = m; __syncthreads();
    for (int s = 128; s > 0; s >>= 1) {
        if (tid < s) red[tid] = fmaxf(red[tid], red[tid + s]);
        __syncthreads();
    }
    m = red[0];
    __syncthreads();

    float sum = 0.0f;
    for (int i = tid; i < N; i += 256) {
        float e = expf(r[i] - m);
        r[i] = e;
        sum += e;
    }
    red[tid] = sum; __syncthreads();
    for (int s = 128; s > 0; s >>= 1) {
        if (tid < s) red[tid] += red[tid + s];
        __syncthreads();
    }
    float inv = 1.0f / red[0];
    for (int i = tid; i < N; i += 256) r[i] *= inv;
}

// ---------------- conv3x3 (SAME) ----------------
// tile: 8 out channels x (16 rows x 64 cols). threads (16,16), 4 horiz outputs/thread.
#define CCHUNK 8
#define TILEH 16
#define TILEW 64
#define INH 18
#define INW 66

__global__ __launch_bounds__(256)
void conv3x3_kernel(const float* __restrict__ in, const float* __restrict__ Wo,
                    const float* __restrict__ bo, float* __restrict__ z)
{
    __shared__ float ins[CCHUNK][INH][INW];    // 38 KB
    __shared__ float wsm[CCHUNK][CCHUNK][9];   // 2.3 KB  (wsm[o][c][k])

    const int tx = threadIdx.x, ty = threadIdx.y;
    const int tid = ty * 16 + tx;
    const int x0 = blockIdx.x * TILEW;
    const int y0 = blockIdx.y * TILEH;
    const int bz = blockIdx.z;
    const int b  = bz / (C / CCHUNK);
    const int o0 = (bz % (C / CCHUNK)) * CCHUNK;

    float acc[CCHUNK][4] = {};

    for (int cb = 0; cb < C / CCHUNK; cb++) {
        const int c0 = cb * CCHUNK;
        for (int e = tid; e < CCHUNK * INH * INW; e += 256) {
            int c  = e / (INH * INW);
            int r  = e % (INH * INW);
            int iy = r / INW, ix = r % INW;
            int y = y0 - 1 + iy, x = x0 - 1 + ix;
            float val = 0.0f;
            if (y >= 0 && y < H && x >= 0 && x < W)
                val = in[((long)(b * C + c0 + c)) * S + (long)y * W + x];
            ins[c][iy][ix] = val;
        }
        for (int e = tid; e < CCHUNK * CCHUNK * 9; e += 256) {
            int o = e / (CCHUNK * 9);
            int r = e % (CCHUNK * 9);
            int c = r / 9, k = r % 9;
            wsm[o][c][k] = Wo[((long)(o0 + o) * C + (c0 + c)) * 9 + k];
        }
        __syncthreads();

        #pragma unroll
        for (int c = 0; c < CCHUNK; c++) {
            float iv[3][6];
            #pragma unroll
            for (int dy = 0; dy < 3; dy++)
                #pragma unroll
                for (int dx = 0; dx < 6; dx++)
                    iv[dy][dx] = ins[c][ty + dy][tx * 4 + dx];
            #pragma unroll
            for (int o = 0; o < CCHUNK; o++) {
                float w0 = wsm[o][c][0], w1 = wsm[o][c][1], w2 = wsm[o][c][2];
                float w3 = wsm[o][c][3], w4 = wsm[o][c][4], w5 = wsm[o][c][5];
                float w6 = wsm[o][c][6], w7 = wsm[o][c][7], w8 = wsm[o][c][8];
                #pragma unroll
                for (int j = 0; j < 4; j++) {
                    float s = w0 * iv[0][j];
                    s = fmaf(w1, iv[0][j + 1], s);
                    s = fmaf(w2, iv[0][j + 2], s);
                    s = fmaf(w3, iv[1][j],     s);
                    s = fmaf(w4, iv[1][j + 1], s);
                    s = fmaf(w5, iv[1][j + 2], s);
                    s = fmaf(w6, iv[2][j],     s);
                    s = fmaf(w7, iv[2][j + 1], s);
                    s = fmaf(w8, iv[2][j + 2], s);
                    acc[o][j] += s;
                }
            }
        }
        __syncthreads();
    }

    const int y = y0 + ty, xb = x0 + tx * 4;
    #pragma unroll
    for (int o = 0; o < CCHUNK; o++) {
        float bb = bo[o0 + o];
        float4 v;
        v.x = acc[o][0] + bb;
        v.y = acc[o][1] + bb;
        v.z = acc[o][2] + bb;
        v.w = acc[o][3] + bb;
        *(float4*)(z + ((long)(b * C + o0 + o)) * S + (long)y * W + xb) = v;
    }
}

// ---------------- batchnorm ----------------
__global__ void bn_stats_kernel(const float* __restrict__ z,
                                float* __restrict__ mean, float* __restrict__ var)
{
    int c = blockIdx.x;
    int tid = threadIdx.x;
    float s = 0.0f, s2 = 0.0f;
    for (int b = 0; b < B; b++) {
        const float* p = z + ((long)(b * C + c)) * S;
        for (int i = tid; i < S; i += 256) {
            float v = p[i];
            s  += v;
            s2 += v * v;
        }
    }
    __shared__ float rs[256], rs2[256];
    rs[tid] = s; rs2[tid] = s2; __syncthreads();
    for (int st = 128; st > 0; st >>= 1) {
        if (tid < st) { rs[tid] += rs[tid + st]; rs2[tid] += rs2[tid + st]; }
        __syncthreads();
    }
    if (tid == 0) {
        float inv = 1.0f / (float)(B * S);
        float m = rs[0] * inv;
        mean[c] = m;
        var[c]  = rs2[0] * inv - m * m;
    }
}

__global__ void bn_apply_kernel(float* __restrict__ z,
                                const float* __restrict__ mean, const float* __restrict__ var,
                                const float* __restrict__ gamma, const float* __restrict__ beta)
{
    long idx = (long)blockIdx.x * 256 + threadIdx.x;
    int c = (int)((idx >> 14) & (C - 1));   // S = 2^14
    float v = z[idx];
    float zn = (v - mean[c]) * rsqrtf(var[c] + 1e-5f);
    zn = zn * gamma[c] + beta[c];
    z[idx] = zn >= 0.0f ? zn : 0.2f * zn;
}

// ---------------- orchestration ----------------
extern "C" void kernel_launch(void* const* d_in, const int* in_sizes, int n_in,
                              void* d_out, int out_size)
{
    const float* x     = (const float*)d_in[0];
    const float* y     = (const float*)d_in[1];
    const float* Wq    = (const float*)d_in[2];
    const float* bq    = (const float*)d_in[3];
    const float* Wk    = (const float*)d_in[4];
    const float* bk    = (const float*)d_in[5];
    const float* Wv    = (const float*)d_in[6];
    const float* bv    = (const float*)d_in[7];
    const float* Wo    = (const float*)d_in[8];
    const float* bo    = (const float*)d_in[9];
    const float* gamma = (const float*)d_in[10];
    const float* beta  = (const float*)d_in[11];
    float* out = (float*)d_out;

    float *q, *k, *v, *att, *qt, *kt, *vt, *ot, *sc, *mean, *var;
    cudaGetSymbolAddress((void**)&q,   g_q);
    cudaGetSymbolAddress((void**)&k,   g_k);
    cudaGetSymbolAddress((void**)&v,   g_v);
    cudaGetSymbolAddress((void**)&att, g_att);
    cudaGetSymbolAddress((void**)&qt,  g_qt);
    cudaGetSymbolAddress((void**)&kt,  g_kt);
    cudaGetSymbolAddress((void**)&vt,  g_vt);
    cudaGetSymbolAddress((void**)&ot,  g_ot);
    cudaGetSymbolAddress((void**)&sc,  g_sc);
    cudaGetSymbolAddress((void**)&mean, g_mean);
    cudaGetSymbolAddress((void**)&var,  g_var);

    const long bstride = (long)C * S;

    // QKV projections: [256 x 16384] = W[256x256] * in[256x16384] per batch
    dim3 gproj(S / 64, C / 64, B);
    gemm_kernel<false><<<gproj, 256>>>(Wq, 0, x, bstride, q, bstride, bq, C, S, C, 1.0f);
    gemm_kernel<false><<<gproj, 256>>>(Wk, 0, y, bstride, k, bstride, bk, C, S, C, 1.0f);
    gemm_kernel<false><<<gproj, 256>>>(Wv, 0, y, bstride, v, bstride, bv, C, S, C, 1.0f);

    const int ps[NSCALE] = {2, 4, 8, 16};
    for (int i = 0; i < NSCALE; i++) {
        int p    = ps[i];
        int outw = W / p;
        int Ni   = outw * outw;
        int Di   = DKC * p * p;
        long tstride = (long)Ni * Di;   // = 1048576

        gather_qkv<<<(B * Ni * Di) / 256, 256>>>(q, k, v, qt, kt, vt, i * DKC, p, outw, Ni, Di);

        // scores = (1/sqrt(Di)) * Qt * Kt^T   [Ni x Ni]
        dim3 gs(Ni / 64, Ni / 64, B);
        gemm_kernel<true><<<gs, 256>>>(qt, tstride, kt, tstride, sc, (long)Ni * Ni,
                                       nullptr, Ni, Ni, Di, 1.0f / sqrtf((float)Di));

        softmax_kernel<<<B * Ni, 256>>>(sc, Ni);

        // O = P * Vt   [Ni x Di]
        dim3 gp(Di / 64, Ni / 64, B);
        gemm_kernel<false><<<gp, 256>>>(sc, (long)Ni * Ni, vt, tstride, ot, tstride,
                                        nullptr, Ni, Di, Ni, 1.0f);

        scatter_out<<<(B * Ni * Di) / 256, 256>>>(ot, att, i * DKC, p, outw, Ni, Di);
    }

    // conv3x3 -> d_out, then BN stats + apply in place
    dim3 gc(W / TILEW, H / TILEH, B * (C / CCHUNK));
    conv3x3_kernel<<<gc, dim3(16, 16)>>>(att, Wo, bo, out);

    bn_stats_kernel<<<C, 256>>>(out, mean, var);
    bn_apply_kernel<<<((long)B * C * S) / 256, 256>>>(out, mean, var, gamma, beta);
}